// round 10
// baseline (speedup 1.0000x reference)
#include <cuda_runtime.h>

// Bilateral 5x5, sigma_color = sigma_space = 1.1, reflect pad, (16,3,512,512) f32.
//
// out = sum_k w_k*s_k*p_k / sum_k w_k*s_k,  w_k = exp(-a*diff^2), a = 1/(2*1.1^2);
// the reference's two normalizations cancel. exp(-a*u), u in [0,1], is a deg-2
// Chebyshev poly. Horizontal spatial weight folded into the poly coefficients
// (3 sets); vertical weight applied once per row; accumulators init from the
// first row (no zero-init).
//
// R10: 512-thread blocks, TILE 64x32 (2x2 quad per thread, same body as R9):
// halo redundancy 1.33x -> 1.20x, half the block boundaries/barriers.

#define H 512
#define W 512
#define NPLANES 48

#define TILE_W 64
#define TILE_H 32
#define BLK_X 32
#define BLK_Y 16
#define SM_W  68
#define SM_H  36

#define G1f 0.66151464f
#define G2f 0.19149516f

// deg-2 Chebyshev coeffs for exp(-a*u), u in [0,1]
#define Q0 0.99969391f
#define Q1 -0.40757903f
#define Q2 0.06969310f

typedef unsigned long long u64;

__device__ __forceinline__ u64 pk(float lo, float hi) {
    u64 r; asm("mov.b64 %0, {%1, %2};" : "=l"(r) : "f"(lo), "f"(hi)); return r;
}
__device__ __forceinline__ u64 f2add(u64 a, u64 b) {
    u64 d; asm("add.rn.f32x2 %0, %1, %2;" : "=l"(d) : "l"(a), "l"(b)); return d;
}
__device__ __forceinline__ u64 f2sub(u64 a, u64 b) {
    u64 d; asm("sub.rn.f32x2 %0, %1, %2;" : "=l"(d) : "l"(a), "l"(b)); return d;
}
__device__ __forceinline__ u64 f2mul(u64 a, u64 b) {
    u64 d; asm("mul.rn.f32x2 %0, %1, %2;" : "=l"(d) : "l"(a), "l"(b)); return d;
}
__device__ __forceinline__ u64 f2fma(u64 a, u64 b, u64 c) {
    u64 d; asm("fma.rn.f32x2 %0, %1, %2, %3;" : "=l"(d) : "l"(a), "l"(b), "l"(c)); return d;
}
__device__ __forceinline__ void unpk(u64 q, float& lo, float& hi) {
    asm("mov.b64 {%0, %1}, %2;" : "=f"(lo), "=f"(hi) : "l"(q));
}

__device__ __forceinline__ int reflect_idx(int i, int n) {
    if (i < 0)  i = -i;
    if (i >= n) i = 2 * n - 2 - i;
    return i;
}

__global__ __launch_bounds__(BLK_X * BLK_Y, 3)
void bilateral_kernel(const float* __restrict__ in, float* __restrict__ out) {
    // smB[r][c] == smA[r][c+1]  (shifted copy -> odd-offset pairs are aligned LDS.64)
    __shared__ __align__(8) float smA[SM_H][SM_W];
    __shared__ __align__(8) float smB[SM_H][SM_W];

    const int tx = threadIdx.x;
    const int ty = threadIdx.y;
    const int bx = blockIdx.x * TILE_W;
    const int by = blockIdx.y * TILE_H;
    const int pbase = blockIdx.z * (H * W);    // < 2^31, 32-bit safe

    // ---- division-free cooperative tile load (32-bit indexing) ----
    const bool interior = (bx != 0) && (bx != (W - TILE_W)) &&
                          (by != 0) && (by != (H - TILE_H));

    #define STORE_SM(r, c, v)                  \
    {                                          \
        smA[r][c] = (v);                       \
        if ((c) > 0) smB[r][(c) - 1] = (v);    \
    }

    if (interior) {
        const float* src = in + (pbase + (by - 2) * W + (bx - 2));
        #pragma unroll
        for (int rr = 0; rr < 3; rr++) {
            int r = ty + rr * BLK_Y;
            if (r < SM_H) {
                const float* sr = src + r * W;
                #pragma unroll
                for (int cc = 0; cc < 3; cc++) {
                    int c = tx + cc * BLK_X;
                    if (c < SM_W) {
                        float v = sr[c];
                        STORE_SM(r, c, v)
                    }
                }
            }
        }
    } else {
        #pragma unroll
        for (int rr = 0; rr < 3; rr++) {
            int r = ty + rr * BLK_Y;
            if (r < SM_H) {
                int gy = reflect_idx(by - 2 + r, H);
                const float* sr = in + (pbase + gy * W);
                #pragma unroll
                for (int cc = 0; cc < 3; cc++) {
                    int c = tx + cc * BLK_X;
                    if (c < SM_W) {
                        int gx = reflect_idx(bx - 2 + c, W);
                        float v = sr[gx];
                        STORE_SM(r, c, v)
                    }
                }
            }
        }
    }
    #undef STORE_SM
    __syncthreads();

    // horizontally-folded poly coefficient sets: coef = g * {Q2, Q1, Q0}
    const u64 A2 = pk(Q2, Q2);                          // g = 1
    const u64 A1 = pk(Q1, Q1);
    const u64 A0 = pk(Q0, Q0);
    const u64 B2 = pk(0.04610273f, 0.04610273f);        // g = G1
    const u64 B1 = pk(-0.26961989f, -0.26961989f);
    const u64 B0 = pk(0.66131215f, 0.66131215f);
    const u64 E2 = pk(0.01334589f, 0.01334589f);        // g = G2
    const u64 E1 = pk(-0.07804951f, -0.07804951f);
    const u64 E0 = pk(0.19143654f, 0.19143654f);
    const u64 GV1 = pk(G1f, G1f);
    const u64 GV2 = pk(G2f, G2f);

    const int col = 2 * tx;
    const int rb  = 2 * ty;

    const u64 ctrA = *(const u64*)&smA[rb + 2][col + 2];
    const u64 ctrB = *(const u64*)&smA[rb + 3][col + 2];

    u64 numA, denA, numB, denB;

    #define ROWLOAD(r)                                  \
        const float* rA = &smA[rb + (r)][col];          \
        const float* rB = &smB[rb + (r)][col];          \
        u64 p0 = *(const u64*)(rA + 0);                 \
        u64 p1 = *(const u64*)(rB + 0);                 \
        u64 p2 = *(const u64*)(rA + 2);                 \
        u64 p3 = *(const u64*)(rB + 2);                 \
        u64 p4 = *(const u64*)(rA + 4);

    #define TAPW(P, K2, K1, K0, WOUT)                   \
        u64 WOUT;                                       \
        {                                               \
            u64 dd = f2sub((P), ctr);                   \
            u64 uu = f2mul(dd, dd);                     \
            u64 tt = f2fma((K2), uu, (K1));             \
            WOUT = f2fma(tt, uu, (K0));                 \
        }

    // produce row sums rn, rd against center CTR
    #define ROWTAPS(CTR, RN, RD)                        \
        u64 RN, RD;                                     \
        {                                               \
            u64 ctr = (CTR);                            \
            TAPW(p0, E2, E1, E0, w0)                    \
            RD = w0;                                    \
            RN = f2mul(w0, p0);                         \
            TAPW(p1, B2, B1, B0, w1)                    \
            RD = f2add(RD, w1);                         \
            RN = f2fma(w1, p1, RN);                     \
            TAPW(p2, A2, A1, A0, w2)                    \
            RD = f2add(RD, w2);                         \
            RN = f2fma(w2, p2, RN);                     \
            TAPW(p3, B2, B1, B0, w3)                    \
            RD = f2add(RD, w3);                         \
            RN = f2fma(w3, p3, RN);                     \
            TAPW(p4, E2, E1, E0, w4)                    \
            RD = f2add(RD, w4);                         \
            RN = f2fma(w4, p4, RN);                     \
        }

    {   // row 0: A only (vertical weight G2) — init A
        ROWLOAD(0)
        ROWTAPS(ctrA, rn, rd)
        denA = f2mul(GV2, rd);
        numA = f2mul(GV2, rn);
    }
    {   // row 1: A (G1), B (G2, init)
        ROWLOAD(1)
        { ROWTAPS(ctrA, rn, rd)
          denA = f2fma(GV1, rd, denA); numA = f2fma(GV1, rn, numA); }
        { ROWTAPS(ctrB, rn, rd)
          denB = f2mul(GV2, rd);       numB = f2mul(GV2, rn); }
    }
    {   // row 2: A (unit), B (G1)
        ROWLOAD(2)
        { ROWTAPS(ctrA, rn, rd)
          denA = f2add(denA, rd);      numA = f2add(numA, rn); }
        { ROWTAPS(ctrB, rn, rd)
          denB = f2fma(GV1, rd, denB); numB = f2fma(GV1, rn, numB); }
    }
    {   // row 3: A (G1), B (unit)
        ROWLOAD(3)
        { ROWTAPS(ctrA, rn, rd)
          denA = f2fma(GV1, rd, denA); numA = f2fma(GV1, rn, numA); }
        { ROWTAPS(ctrB, rn, rd)
          denB = f2add(denB, rd);      numB = f2add(numB, rn); }
    }
    {   // row 4: A (G2), B (G1)
        ROWLOAD(4)
        { ROWTAPS(ctrA, rn, rd)
          denA = f2fma(GV2, rd, denA); numA = f2fma(GV2, rn, numA); }
        { ROWTAPS(ctrB, rn, rd)
          denB = f2fma(GV1, rd, denB); numB = f2fma(GV1, rn, numB); }
    }
    {   // row 5: B only (G2)
        ROWLOAD(5)
        ROWTAPS(ctrB, rn, rd)
        denB = f2fma(GV2, rd, denB);
        numB = f2fma(GV2, rn, numB);
    }

    #undef ROWTAPS
    #undef TAPW
    #undef ROWLOAD

    float na0, na1, da0, da1, nb0, nb1, db0, db1;
    unpk(numA, na0, na1);
    unpk(denA, da0, da1);
    unpk(numB, nb0, nb1);
    unpk(denB, db0, db1);

    float2 oA, oB;
    oA.x = __fdividef(na0, da0);
    oA.y = __fdividef(na1, da1);
    oB.x = __fdividef(nb0, db0);
    oB.y = __fdividef(nb1, db1);

    float* op = out + (pbase + (by + rb) * W + bx + col);
    *(float2*)op       = oA;
    *(float2*)(op + W) = oB;
}

extern "C" void kernel_launch(void* const* d_in, const int* in_sizes, int n_in,
                              void* d_out, int out_size) {
    const float* x = (const float*)d_in[0];
    float* y = (float*)d_out;
    dim3 block(BLK_X, BLK_Y);
    dim3 grid(W / TILE_W, H / TILE_H, NPLANES);
    bilateral_kernel<<<grid, block>>>(x, y);
}

// round 11
// speedup vs baseline: 1.0516x; 1.0516x over previous
#include <cuda_runtime.h>

// Bilateral 5x5, sigma_color = sigma_space = 1.1, reflect pad, (16,3,512,512) f32.
//
// out = sum_k w_k*s_k*p_k / sum_k w_k*s_k,  w_k = exp(-a*diff^2), a = 1/(2*1.1^2);
// the reference's two normalizations cancel. exp(-a*u), u in [0,1], is a deg-2
// Chebyshev poly. Horizontal spatial weight folded into the poly coefficients
// (3 sets); vertical weight applied once per row; accumulators init from the
// first row (no zero-init).
//
// R11: R9 geometry (256-thread CTA, 2x2 quad/thread) + launch_bounds(256,7)
// (36-reg cap -> 87.5% occ ceiling) + merged shared array (one base pointer,
// immediate-offset LDS for the shifted copy).

#define H 512
#define W 512
#define NPLANES 48

#define TILE_W 64
#define TILE_H 16
#define BLK_X 32
#define BLK_Y 8
#define SM_W  68
#define SM_H  20

#define G1f 0.66151464f
#define G2f 0.19149516f

// deg-2 Chebyshev coeffs for exp(-a*u), u in [0,1]
#define Q0 0.99969391f
#define Q1 -0.40757903f
#define Q2 0.06969310f

typedef unsigned long long u64;

__device__ __forceinline__ u64 pk(float lo, float hi) {
    u64 r; asm("mov.b64 %0, {%1, %2};" : "=l"(r) : "f"(lo), "f"(hi)); return r;
}
__device__ __forceinline__ u64 f2add(u64 a, u64 b) {
    u64 d; asm("add.rn.f32x2 %0, %1, %2;" : "=l"(d) : "l"(a), "l"(b)); return d;
}
__device__ __forceinline__ u64 f2sub(u64 a, u64 b) {
    u64 d; asm("sub.rn.f32x2 %0, %1, %2;" : "=l"(d) : "l"(a), "l"(b)); return d;
}
__device__ __forceinline__ u64 f2mul(u64 a, u64 b) {
    u64 d; asm("mul.rn.f32x2 %0, %1, %2;" : "=l"(d) : "l"(a), "l"(b)); return d;
}
__device__ __forceinline__ u64 f2fma(u64 a, u64 b, u64 c) {
    u64 d; asm("fma.rn.f32x2 %0, %1, %2, %3;" : "=l"(d) : "l"(a), "l"(b), "l"(c)); return d;
}
__device__ __forceinline__ void unpk(u64 q, float& lo, float& hi) {
    asm("mov.b64 {%0, %1}, %2;" : "=f"(lo), "=f"(hi) : "l"(q));
}

__device__ __forceinline__ int reflect_idx(int i, int n) {
    if (i < 0)  i = -i;
    if (i >= n) i = 2 * n - 2 - i;
    return i;
}

__global__ __launch_bounds__(BLK_X * BLK_Y, 7)
void bilateral_kernel(const float* __restrict__ in, float* __restrict__ out) {
    // sm[0] = tile; sm[1][r][c] == sm[0][r][c+1] (shifted copy, fixed byte
    // offset from the same base -> immediate-offset LDS.64 for odd pairs)
    __shared__ __align__(8) float sm[2][SM_H][SM_W];

    const int tx = threadIdx.x;
    const int ty = threadIdx.y;
    const int bx = blockIdx.x * TILE_W;
    const int by = blockIdx.y * TILE_H;
    const int pbase = blockIdx.z * (H * W);    // < 2^31, 32-bit safe

    // ---- division-free cooperative tile load (32-bit indexing) ----
    const bool interior = (bx != 0) && (bx != (W - TILE_W)) &&
                          (by != 0) && (by != (H - TILE_H));

    #define STORE_SM(r, c, v)                      \
    {                                              \
        sm[0][r][c] = (v);                         \
        if ((c) > 0) sm[1][r][(c) - 1] = (v);      \
    }

    if (interior) {
        const float* src = in + (pbase + (by - 2) * W + (bx - 2));
        #pragma unroll
        for (int rr = 0; rr < 3; rr++) {
            int r = ty + rr * BLK_Y;
            if (r < SM_H) {
                const float* sr = src + r * W;
                #pragma unroll
                for (int cc = 0; cc < 3; cc++) {
                    int c = tx + cc * BLK_X;
                    if (c < SM_W) {
                        float v = sr[c];
                        STORE_SM(r, c, v)
                    }
                }
            }
        }
    } else {
        #pragma unroll
        for (int rr = 0; rr < 3; rr++) {
            int r = ty + rr * BLK_Y;
            if (r < SM_H) {
                int gy = reflect_idx(by - 2 + r, H);
                const float* sr = in + (pbase + gy * W);
                #pragma unroll
                for (int cc = 0; cc < 3; cc++) {
                    int c = tx + cc * BLK_X;
                    if (c < SM_W) {
                        int gx = reflect_idx(bx - 2 + c, W);
                        float v = sr[gx];
                        STORE_SM(r, c, v)
                    }
                }
            }
        }
    }
    #undef STORE_SM
    __syncthreads();

    // horizontally-folded poly coefficient sets: coef = g * {Q2, Q1, Q0}
    const u64 A2 = pk(Q2, Q2);                          // g = 1
    const u64 A1 = pk(Q1, Q1);
    const u64 A0 = pk(Q0, Q0);
    const u64 B2 = pk(0.04610273f, 0.04610273f);        // g = G1
    const u64 B1 = pk(-0.26961989f, -0.26961989f);
    const u64 B0 = pk(0.66131215f, 0.66131215f);
    const u64 E2 = pk(0.01334589f, 0.01334589f);        // g = G2
    const u64 E1 = pk(-0.07804951f, -0.07804951f);
    const u64 E0 = pk(0.19143654f, 0.19143654f);
    const u64 GV1 = pk(G1f, G1f);
    const u64 GV2 = pk(G2f, G2f);

    const int col = 2 * tx;
    const int rb  = 2 * ty;

    const u64 ctrA = *(const u64*)&sm[0][rb + 2][col + 2];
    const u64 ctrB = *(const u64*)&sm[0][rb + 3][col + 2];

    u64 numA, denA, numB, denB;

    // single base pointer per row; shifted copy reached via constant offset
    #define SM_SHIFT (SM_H * SM_W)   // floats between sm[0] and sm[1]

    #define ROWLOAD(r)                                  \
        const float* rA = &sm[0][rb + (r)][col];        \
        u64 p0 = *(const u64*)(rA + 0);                 \
        u64 p1 = *(const u64*)(rA + SM_SHIFT + 0);      \
        u64 p2 = *(const u64*)(rA + 2);                 \
        u64 p3 = *(const u64*)(rA + SM_SHIFT + 2);      \
        u64 p4 = *(const u64*)(rA + 4);

    #define TAPW(P, K2, K1, K0, WOUT)                   \
        u64 WOUT;                                       \
        {                                               \
            u64 dd = f2sub((P), ctr);                   \
            u64 uu = f2mul(dd, dd);                     \
            u64 tt = f2fma((K2), uu, (K1));             \
            WOUT = f2fma(tt, uu, (K0));                 \
        }

    // produce row sums rn, rd against center CTR
    #define ROWTAPS(CTR, RN, RD)                        \
        u64 RN, RD;                                     \
        {                                               \
            u64 ctr = (CTR);                            \
            TAPW(p0, E2, E1, E0, w0)                    \
            RD = w0;                                    \
            RN = f2mul(w0, p0);                         \
            TAPW(p1, B2, B1, B0, w1)                    \
            RD = f2add(RD, w1);                         \
            RN = f2fma(w1, p1, RN);                     \
            TAPW(p2, A2, A1, A0, w2)                    \
            RD = f2add(RD, w2);                         \
            RN = f2fma(w2, p2, RN);                     \
            TAPW(p3, B2, B1, B0, w3)                    \
            RD = f2add(RD, w3);                         \
            RN = f2fma(w3, p3, RN);                     \
            TAPW(p4, E2, E1, E0, w4)                    \
            RD = f2add(RD, w4);                         \
            RN = f2fma(w4, p4, RN);                     \
        }

    {   // row 0: A only (vertical weight G2) — init A
        ROWLOAD(0)
        ROWTAPS(ctrA, rn, rd)
        denA = f2mul(GV2, rd);
        numA = f2mul(GV2, rn);
    }
    {   // row 1: A (G1), B (G2, init)
        ROWLOAD(1)
        { ROWTAPS(ctrA, rn, rd)
          denA = f2fma(GV1, rd, denA); numA = f2fma(GV1, rn, numA); }
        { ROWTAPS(ctrB, rn, rd)
          denB = f2mul(GV2, rd);       numB = f2mul(GV2, rn); }
    }
    {   // row 2: A (unit), B (G1)
        ROWLOAD(2)
        { ROWTAPS(ctrA, rn, rd)
          denA = f2add(denA, rd);      numA = f2add(numA, rn); }
        { ROWTAPS(ctrB, rn, rd)
          denB = f2fma(GV1, rd, denB); numB = f2fma(GV1, rn, numB); }
    }
    {   // row 3: A (G1), B (unit)
        ROWLOAD(3)
        { ROWTAPS(ctrA, rn, rd)
          denA = f2fma(GV1, rd, denA); numA = f2fma(GV1, rn, numA); }
        { ROWTAPS(ctrB, rn, rd)
          denB = f2add(denB, rd);      numB = f2add(numB, rn); }
    }
    {   // row 4: A (G2), B (G1)
        ROWLOAD(4)
        { ROWTAPS(ctrA, rn, rd)
          denA = f2fma(GV2, rd, denA); numA = f2fma(GV2, rn, numA); }
        { ROWTAPS(ctrB, rn, rd)
          denB = f2fma(GV1, rd, denB); numB = f2fma(GV1, rn, numB); }
    }
    {   // row 5: B only (G2)
        ROWLOAD(5)
        ROWTAPS(ctrB, rn, rd)
        denB = f2fma(GV2, rd, denB);
        numB = f2fma(GV2, rn, numB);
    }

    #undef ROWTAPS
    #undef TAPW
    #undef ROWLOAD
    #undef SM_SHIFT

    float na0, na1, da0, da1, nb0, nb1, db0, db1;
    unpk(numA, na0, na1);
    unpk(denA, da0, da1);
    unpk(numB, nb0, nb1);
    unpk(denB, db0, db1);

    float2 oA, oB;
    oA.x = __fdividef(na0, da0);
    oA.y = __fdividef(na1, da1);
    oB.x = __fdividef(nb0, db0);
    oB.y = __fdividef(nb1, db1);

    float* op = out + (pbase + (by + rb) * W + bx + col);
    *(float2*)op       = oA;
    *(float2*)(op + W) = oB;
}

extern "C" void kernel_launch(void* const* d_in, const int* in_sizes, int n_in,
                              void* d_out, int out_size) {
    const float* x = (const float*)d_in[0];
    float* y = (float*)d_out;
    dim3 block(BLK_X, BLK_Y);
    dim3 grid(W / TILE_W, H / TILE_H, NPLANES);
    bilateral_kernel<<<grid, block>>>(x, y);
}